// round 10
// baseline (speedup 1.0000x reference)
#include <cuda_runtime.h>
#include <cuda_bf16.h>
#include <cstddef>

// Problem constants (shapes fixed by the dataset)
#define NPTS   8192
#define DIM    256
#define KR     5      // kmeans runs
#define NC     64     // clusters per run
#define TK     8      // top_k
#define NITER  20

// ---------------- device scratch (static globals; no allocation) ----------------
__device__ float    g_sim[(size_t)NPTS * NPTS];          // 256 MB similarity matrix
__device__ unsigned g_bitmap[(size_t)NPTS * NPTS / 32];  // 8 MB adjacency bitmap
__device__ float    g_cent[KR * NC * DIM];
__device__ float    g_cnorm[KR * NC];
__device__ float    g_sums[KR * NC * DIM];
__device__ float    g_counts[KR * NC];
__device__ int      g_labels[KR * NPTS];
__device__ int      g_Iknn[NPTS * TK];
__device__ float    g_Dknn[NPTS * TK];

// ---------------- packed f32x2 helpers ----------------
__device__ __forceinline__ unsigned long long pack2(float lo, float hi) {
    unsigned long long d;
    asm("mov.b64 %0, {%1, %2};" : "=l"(d) : "f"(lo), "f"(hi));
    return d;
}
__device__ __forceinline__ unsigned long long dup2(float v) {
    unsigned long long d;
    asm("mov.b64 %0, {%1, %1};" : "=l"(d) : "f"(v));
    return d;
}
__device__ __forceinline__ void unpack2(unsigned long long d, float& lo, float& hi) {
    asm("mov.b64 {%0, %1}, %2;" : "=f"(lo), "=f"(hi) : "l"(d));
}
__device__ __forceinline__ void ffma2(unsigned long long& d, unsigned long long a,
                                      unsigned long long b) {
    asm("fma.rn.f32x2 %0, %1, %2, %0;" : "+l"(d) : "l"(a), "l"(b));
}

// ---------------- adjacency bitmap ----------------
__global__ void set_edges_kernel(const int* __restrict__ eidx, int E) {
    int t = blockIdx.x * blockDim.x + threadIdx.x;
    if (t < E) {
        int a = eidx[t];
        int b = eidx[E + t];
        unsigned code = (unsigned)a * NPTS + (unsigned)b;
        atomicOr(&g_bitmap[code >> 5], 1u << (code & 31));
    }
}

// ---------------- kmeans: init centroids (gather + norms); also zero accumulators ----------------
__global__ void kinit_kernel(const float* __restrict__ X, const int* __restrict__ init_idx) {
    int rc = blockIdx.x;               // 0..KR*NC-1
    int src = init_idx[rc];
    float v = X[(size_t)src * DIM + threadIdx.x];
    g_cent[(size_t)rc * DIM + threadIdx.x] = v;
    // zero accumulators for the first Lloyd step (update_kernel re-zeros thereafter)
    g_sums[(size_t)rc * DIM + threadIdx.x] = 0.0f;
    if (threadIdx.x == 0) g_counts[rc] = 0.0f;
    __shared__ float red[256];
    red[threadIdx.x] = v * v;
    __syncthreads();
    for (int s = 128; s > 0; s >>= 1) {
        if (threadIdx.x < s) red[threadIdx.x] += red[threadIdx.x + s];
        __syncthreads();
    }
    if (threadIdx.x == 0) g_cnorm[rc] = red[0];
}

// ---------------- kmeans: assign (argmin_c ||c||^2 - 2 x.c) ----------------
// grid (NPTS/128, KR), block 256. 128 pts x 64 clusters tile; per-thread 8x4
// (8x2 packed f32x2). A-operand smem traffic amortized 2x vs 64-pt tile.
__global__ void assign_kernel(const float* __restrict__ X) {
    int r = blockIdx.y;
    int pbase = blockIdx.x * 128;
    __shared__ float Xs[16][128];
    __shared__ float Cs[16][64];
    __shared__ float dots[128][65];
    __shared__ float cn[64];
    int tid = threadIdx.x;
    int ty = tid >> 4, tx = tid & 15;     // ty: 16 point-groups of 8, tx: 16 cluster-groups of 4
    unsigned long long acc2[8][2];
#pragma unroll
    for (int i = 0; i < 8; i++)
#pragma unroll
        for (int j = 0; j < 2; j++) acc2[i][j] = 0ull;  // (+0.0f, +0.0f)
    int xrow = tid >> 1;                  // 128 rows
    int xkq = (tid & 1) * 8;              // two float4 per thread
    int crow = tid >> 2;                  // 64 rows
    int ckq = (tid & 3) * 4;
    for (int k0 = 0; k0 < DIM; k0 += 16) {
        float4 a4 = *(const float4*)&X[(size_t)(pbase + xrow) * DIM + k0 + xkq];
        float4 a4b = *(const float4*)&X[(size_t)(pbase + xrow) * DIM + k0 + xkq + 4];
        float4 b4 = *(const float4*)&g_cent[(size_t)(r * NC + crow) * DIM + k0 + ckq];
        Xs[xkq + 0][xrow] = a4.x;  Xs[xkq + 1][xrow] = a4.y;
        Xs[xkq + 2][xrow] = a4.z;  Xs[xkq + 3][xrow] = a4.w;
        Xs[xkq + 4][xrow] = a4b.x; Xs[xkq + 5][xrow] = a4b.y;
        Xs[xkq + 6][xrow] = a4b.z; Xs[xkq + 7][xrow] = a4b.w;
        Cs[ckq + 0][crow] = b4.x;  Cs[ckq + 1][crow] = b4.y;
        Cs[ckq + 2][crow] = b4.z;  Cs[ckq + 3][crow] = b4.w;
        __syncthreads();
#pragma unroll
        for (int kk = 0; kk < 16; kk++) {
            unsigned long long a2[8], b2[2];
#pragma unroll
            for (int i = 0; i < 8; i++) a2[i] = dup2(Xs[kk][ty * 8 + i]);
#pragma unroll
            for (int j = 0; j < 2; j++) {
                float2 b = *(const float2*)&Cs[kk][tx * 4 + j * 2];
                b2[j] = pack2(b.x, b.y);
            }
#pragma unroll
            for (int i = 0; i < 8; i++)
#pragma unroll
                for (int j = 0; j < 2; j++) ffma2(acc2[i][j], a2[i], b2[j]);
        }
        __syncthreads();
    }
#pragma unroll
    for (int i = 0; i < 8; i++)
#pragma unroll
        for (int j = 0; j < 2; j++) {
            float lo, hi;
            unpack2(acc2[i][j], lo, hi);
            dots[ty * 8 + i][tx * 4 + j * 2 + 0] = lo;
            dots[ty * 8 + i][tx * 4 + j * 2 + 1] = hi;
        }
    if (tid < 64) cn[tid] = g_cnorm[r * NC + tid];
    __syncthreads();
    if (tid < 128) {
        int p = tid;
        float best = 1e30f;
        int bi = 0;
        for (int c = 0; c < NC; c++) {
            float d2 = cn[c] - 2.0f * dots[p][c];
            if (d2 < best) { best = d2; bi = c; }   // strict < -> first-min, matches jnp.argmin
        }
        g_labels[r * NPTS + pbase + p] = bi;
    }
}

// ---------------- kmeans: scatter segment sums (warp-parallel smem atomics) ----------------
// grid (NPTS/256, KR), block 256, dynamic smem = NC*DIM floats (+NC counts).
// Each warp owns 32 points; per point the warp loads all 256 dims coalesced and
// accumulates via spread-address smem atomics (distinct banks within warp -> fast).
#define SCAT_PTS 256
__global__ void scatter_kernel(const float* __restrict__ X) {
    extern __shared__ float sh[];                // [NC][DIM] acc + [NC] counts
    float* acc = sh;                             // NC*DIM
    float* cnt = sh + NC * DIM;                  // NC
    int r = blockIdx.y;
    int pbase = blockIdx.x * SCAT_PTS;
    int tid = threadIdx.x;
    int w = tid >> 5, lane = tid & 31;
    for (int i = tid; i < NC * DIM; i += 256) acc[i] = 0.0f;
    if (tid < NC) cnt[tid] = 0.0f;
    __syncthreads();
    const int* lbl = g_labels + r * NPTS + pbase + w * 32;
#pragma unroll 2
    for (int i = 0; i < 32; i++) {
        int p = pbase + w * 32 + i;
        int l = lbl[i];                                      // uniform in warp -> broadcast
        const float* xp = X + (size_t)p * DIM;
#pragma unroll
        for (int k = 0; k < 8; k++)
            atomicAdd(&acc[l * DIM + lane + 32 * k], xp[lane + 32 * k]);
        if (lane == 0) atomicAdd(&cnt[l], 1.0f);
    }
    __syncthreads();
    for (int i = tid; i < NC * DIM; i += 256)
        atomicAdd(&g_sums[(size_t)r * NC * DIM + i], acc[i]);
    if (tid < NC) atomicAdd(&g_counts[r * NC + tid], cnt[tid]);
}

// ---------------- kmeans: centroid update + norms; re-zero accumulators for next iter ----------------
__global__ void update_kernel() {
    int rc = blockIdx.x;
    float cnt = g_counts[rc];
    float v = g_cent[(size_t)rc * DIM + threadIdx.x];
    if (cnt > 0.0f) v = g_sums[(size_t)rc * DIM + threadIdx.x] / fmaxf(cnt, 1.0f);
    g_cent[(size_t)rc * DIM + threadIdx.x] = v;
    g_sums[(size_t)rc * DIM + threadIdx.x] = 0.0f;
    if (threadIdx.x == 0) g_counts[rc] = 0.0f;
    __shared__ float red[256];
    red[threadIdx.x] = v * v;
    __syncthreads();
    for (int s = 128; s > 0; s >>= 1) {
        if (threadIdx.x < s) red[threadIdx.x] += red[threadIdx.x + s];
        __syncthreads();
    }
    if (threadIdx.x == 0) g_cnorm[rc] = red[0];
}

// ---------------- big GEMM: sim = student @ teacher^T (+10 on diag) ----------------
// 128x128 tiles, Bk=8, 256 threads, 8x8 per-thread tile as 8x4 packed f32x2 accs.
// Double-buffered smem with register prefetch: one syncthreads per k-block, LDG
// latency overlapped with compute.
__global__ void gemm_sim_kernel(const float* __restrict__ A, const float* __restrict__ B) {
    __shared__ float As[2][8][128];
    __shared__ float Bs[2][8][128];
    int bi = blockIdx.y * 128, bj = blockIdx.x * 128;
    int tid = threadIdx.x;
    int tx = tid & 15, ty = tid >> 4;
    unsigned long long acc2[8][4];
#pragma unroll
    for (int i = 0; i < 8; i++)
#pragma unroll
        for (int j = 0; j < 4; j++) acc2[i][j] = 0ull;  // (+0.0f, +0.0f)
    int lr = tid >> 1;
    int kq = (tid & 1) * 4;
    const float* Arow = A + (size_t)(bi + lr) * DIM + kq;
    const float* Brow = B + (size_t)(bj + lr) * DIM + kq;

    // prologue: fill buffer 0
    {
        float4 a4 = *(const float4*)Arow;
        float4 b4 = *(const float4*)Brow;
        As[0][kq + 0][lr] = a4.x; As[0][kq + 1][lr] = a4.y;
        As[0][kq + 2][lr] = a4.z; As[0][kq + 3][lr] = a4.w;
        Bs[0][kq + 0][lr] = b4.x; Bs[0][kq + 1][lr] = b4.y;
        Bs[0][kq + 2][lr] = b4.z; Bs[0][kq + 3][lr] = b4.w;
    }
    __syncthreads();

    for (int k0 = 0; k0 < DIM; k0 += 8) {
        int buf = (k0 >> 3) & 1;
        bool has_next = (k0 + 8 < DIM);
        float4 a4n, b4n;
        if (has_next) {
            a4n = *(const float4*)(Arow + k0 + 8);
            b4n = *(const float4*)(Brow + k0 + 8);
        }
#pragma unroll
        for (int kk = 0; kk < 8; kk++) {
            unsigned long long a2[8], b2[4];
#pragma unroll
            for (int i = 0; i < 8; i++) a2[i] = dup2(As[buf][kk][ty * 8 + i]);
#pragma unroll
            for (int j = 0; j < 4; j++) {
                float2 b = *(const float2*)&Bs[buf][kk][tx * 8 + j * 2];
                b2[j] = pack2(b.x, b.y);
            }
#pragma unroll
            for (int i = 0; i < 8; i++)
#pragma unroll
                for (int j = 0; j < 4; j++) ffma2(acc2[i][j], a2[i], b2[j]);
        }
        if (has_next) {
            int nb = buf ^ 1;
            As[nb][kq + 0][lr] = a4n.x; As[nb][kq + 1][lr] = a4n.y;
            As[nb][kq + 2][lr] = a4n.z; As[nb][kq + 3][lr] = a4n.w;
            Bs[nb][kq + 0][lr] = b4n.x; Bs[nb][kq + 1][lr] = b4n.y;
            Bs[nb][kq + 2][lr] = b4n.z; Bs[nb][kq + 3][lr] = b4n.w;
            __syncthreads();
        }
    }
#pragma unroll
    for (int i = 0; i < 8; i++) {
        int gi = bi + ty * 8 + i;
#pragma unroll
        for (int j = 0; j < 4; j++) {
            int gj = bj + tx * 8 + j * 2;
            float lo, hi;
            unpack2(acc2[i][j], lo, hi);
            if (gi == gj) lo += 10.0f;
            if (gi == gj + 1) hi += 10.0f;
            float2 vv = make_float2(lo, hi);
            *(float2*)&g_sim[(size_t)gi * NPTS + gj] = vv;
        }
    }
}

// ---------------- top-8 per row ----------------
// one block (256 threads) per row; float4 scan (4x fewer LDG), per-thread sorted
// top-8 (ties keep first/lowest index), then smem tournament merge.
__global__ void topk_kernel() {
    int row = blockIdx.x;
    const float4* s4 = (const float4*)(g_sim + (size_t)row * NPTS);
    int tid = threadIdx.x;
    float v[TK];
    int id[TK];
#pragma unroll
    for (int t = 0; t < TK; t++) { v[t] = -1e30f; id[t] = 0x7fffffff; }
    for (int q = tid; q < NPTS / 4; q += 256) {     // q scans ascending -> indices ascending
        float4 x4 = s4[q];
        float xs[4] = {x4.x, x4.y, x4.z, x4.w};
#pragma unroll
        for (int e = 0; e < 4; e++) {
            float x = xs[e];
            if (x > v[TK - 1]) {
                int j = q * 4 + e;
                v[TK - 1] = x; id[TK - 1] = j;
#pragma unroll
                for (int t = TK - 1; t > 0; t--) {
                    if (v[t] > v[t - 1]) {
                        float tv = v[t]; v[t] = v[t - 1]; v[t - 1] = tv;
                        int ti = id[t]; id[t] = id[t - 1]; id[t - 1] = ti;
                    }
                }
            }
        }
    }
    __shared__ float sv[256 * TK];
    __shared__ int si[256 * TK];
#pragma unroll
    for (int t = 0; t < TK; t++) { sv[tid * TK + t] = v[t]; si[tid * TK + t] = id[t]; }
    __syncthreads();
    for (int half = 128; half >= 1; half >>= 1) {
        float ov[TK];
        int oi[TK];
        if (tid < half) {
            int ai = 0, bi = 0;
#pragma unroll
            for (int t = 0; t < TK; t++) {
                float av = sv[tid * TK + ai], bv = sv[(tid + half) * TK + bi];
                int aid = si[tid * TK + ai], bid = si[(tid + half) * TK + bi];
                bool takeA = (av > bv) || (av == bv && aid <= bid);  // stable: lower index first
                if (takeA) { ov[t] = av; oi[t] = aid; ai++; }
                else       { ov[t] = bv; oi[t] = bid; bi++; }
            }
#pragma unroll
            for (int t = 0; t < TK; t++) { sv[tid * TK + t] = ov[t]; si[tid * TK + t] = oi[t]; }
        }
        __syncthreads();
    }
    if (tid < TK) {
        g_Dknn[row * TK + tid] = sv[tid];
        g_Iknn[row * TK + tid] = si[tid];
    }
}

// ---------------- finalize: mask + outputs ----------------
// out layout: [I_knn (as float) | pos_mask (0/1) | D_knn], each NPTS*TK
__global__ void finalize_kernel(float* __restrict__ out) {
    int t = blockIdx.x * blockDim.x + threadIdx.x;   // 0..NPTS*TK-1
    if (t >= NPTS * TK) return;
    int i = t >> 3;
    int I = g_Iknn[t];
    unsigned code = (unsigned)i * NPTS + (unsigned)I;
    bool adj = (g_bitmap[code >> 5] >> (code & 31)) & 1u;
    bool close = false;
#pragma unroll
    for (int r = 0; r < KR; r++)
        close = close || (g_labels[r * NPTS + i] == g_labels[r * NPTS + I]);
    out[t] = (float)I;
    out[NPTS * TK + t] = (adj || close) ? 1.0f : 0.0f;
    out[2 * NPTS * TK + t] = g_Dknn[t];
}

// ---------------- launch ----------------
extern "C" void kernel_launch(void* const* d_in, const int* in_sizes, int n_in,
                              void* d_out, int out_size) {
    const float* student = (const float*)d_in[0];
    const float* teacher = (const float*)d_in[1];
    const int* eidx      = (const int*)d_in[2];
    const int* kinit_idx = (const int*)d_in[3];
    // d_in[4] = top_k (known 8; hardcoded as TK)
    float* out = (float*)d_out;
    int E = in_sizes[2] / 2;

    void* bmp_p;
    cudaGetSymbolAddress(&bmp_p, g_bitmap);

    // dynamic smem for scatter: NC*DIM acc + NC counts
    const size_t scat_smem = (size_t)(NC * DIM + NC) * sizeof(float);
    cudaFuncSetAttribute(scatter_kernel, cudaFuncAttributeMaxDynamicSharedMemorySize,
                         (int)scat_smem);

    // adjacency bitmap
    cudaMemsetAsync(bmp_p, 0, (size_t)NPTS * NPTS / 8);
    set_edges_kernel<<<(E + 255) / 256, 256>>>(eidx, E);

    // kmeans (KR parallel runs, NITER sequential Lloyd steps)
    kinit_kernel<<<KR * NC, 256>>>(teacher, kinit_idx);
    for (int it = 0; it < NITER; it++) {
        assign_kernel<<<dim3(NPTS / 128, KR), 256>>>(teacher);
        scatter_kernel<<<dim3(NPTS / SCAT_PTS, KR), 256, scat_smem>>>(teacher);
        update_kernel<<<KR * NC, 256>>>();
    }
    assign_kernel<<<dim3(NPTS / 128, KR), 256>>>(teacher);  // final labels

    // similarity + top-k
    gemm_sim_kernel<<<dim3(NPTS / 128, NPTS / 128), 256>>>(student, teacher);
    topk_kernel<<<NPTS, 256>>>();

    // outputs
    finalize_kernel<<<(NPTS * TK + 255) / 256, 256>>>(out);
}

// round 15
// speedup vs baseline: 1.1614x; 1.1614x over previous
#include <cuda_runtime.h>
#include <cuda_bf16.h>
#include <cstddef>

// Problem constants (shapes fixed by the dataset)
#define NPTS   8192
#define DIM    256
#define KR     5      // kmeans runs
#define NC     64     // clusters per run
#define TK     8      // top_k
#define NITER  20

// ---------------- device scratch (static globals; no allocation) ----------------
__device__ float    g_sim[(size_t)NPTS * NPTS];          // 256 MB similarity matrix
__device__ unsigned g_bitmap[(size_t)NPTS * NPTS / 32];  // 8 MB adjacency bitmap
__device__ float    g_cent[KR * NC * DIM];
__device__ float    g_cnorm[KR * NC];
__device__ float    g_sums[KR * NC * DIM];
__device__ float    g_counts[KR * NC];
__device__ int      g_labels[KR * NPTS];
__device__ int      g_Iknn[NPTS * TK];
__device__ float    g_Dknn[NPTS * TK];

// ---------------- packed f32x2 helpers ----------------
__device__ __forceinline__ unsigned long long pack2(float lo, float hi) {
    unsigned long long d;
    asm("mov.b64 %0, {%1, %2};" : "=l"(d) : "f"(lo), "f"(hi));
    return d;
}
__device__ __forceinline__ unsigned long long dup2(float v) {
    unsigned long long d;
    asm("mov.b64 %0, {%1, %1};" : "=l"(d) : "f"(v));
    return d;
}
__device__ __forceinline__ void unpack2(unsigned long long d, float& lo, float& hi) {
    asm("mov.b64 {%0, %1}, %2;" : "=f"(lo), "=f"(hi) : "l"(d));
}
__device__ __forceinline__ void ffma2(unsigned long long& d, unsigned long long a,
                                      unsigned long long b) {
    asm("fma.rn.f32x2 %0, %1, %2, %0;" : "+l"(d) : "l"(a), "l"(b));
}
__device__ __forceinline__ void add2(unsigned long long& d, unsigned long long a) {
    asm("add.rn.f32x2 %0, %0, %1;" : "+l"(d) : "l"(a));
}

// ---------------- adjacency bitmap ----------------
__global__ void set_edges_kernel(const int* __restrict__ eidx, int E) {
    int t = blockIdx.x * blockDim.x + threadIdx.x;
    if (t < E) {
        int a = eidx[t];
        int b = eidx[E + t];
        unsigned code = (unsigned)a * NPTS + (unsigned)b;
        atomicOr(&g_bitmap[code >> 5], 1u << (code & 31));
    }
}

// ---------------- kmeans: init centroids (gather + norms); also zero accumulators ----------------
__global__ void kinit_kernel(const float* __restrict__ X, const int* __restrict__ init_idx) {
    int rc = blockIdx.x;               // 0..KR*NC-1
    int src = init_idx[rc];
    float v = X[(size_t)src * DIM + threadIdx.x];
    g_cent[(size_t)rc * DIM + threadIdx.x] = v;
    g_sums[(size_t)rc * DIM + threadIdx.x] = 0.0f;
    if (threadIdx.x == 0) g_counts[rc] = 0.0f;
    __shared__ float red[256];
    red[threadIdx.x] = v * v;
    __syncthreads();
    for (int s = 128; s > 0; s >>= 1) {
        if (threadIdx.x < s) red[threadIdx.x] += red[threadIdx.x + s];
        __syncthreads();
    }
    if (threadIdx.x == 0) g_cnorm[rc] = red[0];
}

// ---------------- kmeans: assign (argmin_c ||c||^2 - 2 x.c) ----------------
// grid (NPTS/128, KR), block 256. 128 pts x 64 clusters tile; per-thread 8x4
// (8x2 packed f32x2).
__global__ void assign_kernel(const float* __restrict__ X) {
    int r = blockIdx.y;
    int pbase = blockIdx.x * 128;
    __shared__ float Xs[16][128];
    __shared__ float Cs[16][64];
    __shared__ float dots[128][65];
    __shared__ float cn[64];
    int tid = threadIdx.x;
    int ty = tid >> 4, tx = tid & 15;
    unsigned long long acc2[8][2];
#pragma unroll
    for (int i = 0; i < 8; i++)
#pragma unroll
        for (int j = 0; j < 2; j++) acc2[i][j] = 0ull;
    int xrow = tid >> 1;
    int xkq = (tid & 1) * 8;
    int crow = tid >> 2;
    int ckq = (tid & 3) * 4;
    for (int k0 = 0; k0 < DIM; k0 += 16) {
        float4 a4 = *(const float4*)&X[(size_t)(pbase + xrow) * DIM + k0 + xkq];
        float4 a4b = *(const float4*)&X[(size_t)(pbase + xrow) * DIM + k0 + xkq + 4];
        float4 b4 = *(const float4*)&g_cent[(size_t)(r * NC + crow) * DIM + k0 + ckq];
        Xs[xkq + 0][xrow] = a4.x;  Xs[xkq + 1][xrow] = a4.y;
        Xs[xkq + 2][xrow] = a4.z;  Xs[xkq + 3][xrow] = a4.w;
        Xs[xkq + 4][xrow] = a4b.x; Xs[xkq + 5][xrow] = a4b.y;
        Xs[xkq + 6][xrow] = a4b.z; Xs[xkq + 7][xrow] = a4b.w;
        Cs[ckq + 0][crow] = b4.x;  Cs[ckq + 1][crow] = b4.y;
        Cs[ckq + 2][crow] = b4.z;  Cs[ckq + 3][crow] = b4.w;
        __syncthreads();
#pragma unroll
        for (int kk = 0; kk < 16; kk++) {
            unsigned long long a2[8], b2[2];
#pragma unroll
            for (int i = 0; i < 8; i++) a2[i] = dup2(Xs[kk][ty * 8 + i]);
#pragma unroll
            for (int j = 0; j < 2; j++) {
                float2 b = *(const float2*)&Cs[kk][tx * 4 + j * 2];
                b2[j] = pack2(b.x, b.y);
            }
#pragma unroll
            for (int i = 0; i < 8; i++)
#pragma unroll
                for (int j = 0; j < 2; j++) ffma2(acc2[i][j], a2[i], b2[j]);
        }
        __syncthreads();
    }
#pragma unroll
    for (int i = 0; i < 8; i++)
#pragma unroll
        for (int j = 0; j < 2; j++) {
            float lo, hi;
            unpack2(acc2[i][j], lo, hi);
            dots[ty * 8 + i][tx * 4 + j * 2 + 0] = lo;
            dots[ty * 8 + i][tx * 4 + j * 2 + 1] = hi;
        }
    if (tid < 64) cn[tid] = g_cnorm[r * NC + tid];
    __syncthreads();
    if (tid < 128) {
        int p = tid;
        float best = 1e30f;
        int bi = 0;
        for (int c = 0; c < NC; c++) {
            float d2 = cn[c] - 2.0f * dots[p][c];
            if (d2 < best) { best = d2; bi = c; }   // strict < -> first-min, matches jnp.argmin
        }
        g_labels[r * NPTS + pbase + p] = bi;
    }
}

// ---------------- kmeans: scatter segment sums (one-hot register accumulation) ----------------
// grid (16, DIM/64, KR), block 256. Block owns (run, 64-dim chunk, 512 points).
// Thread (td=tid&15, tc=tid>>4) owns dims [dbase+td*4, +4) x clusters [tc*4, +4)
// in registers. Per point: uniform label, range check, predicated f32x2 adds on
// match (warp-level hit rate ~1/8). No atomics in the hot loop, no serial chain.
#define SCAT_PC  16
#define SCAT_PPB (NPTS / SCAT_PC)   // 512
#define SCAT_SUB 32
__global__ void scatter_kernel(const float* __restrict__ X) {
    __shared__ float Xs[SCAT_SUB][64];
    __shared__ int lbl[SCAT_SUB];
    int r = blockIdx.z;
    int dbase = blockIdx.y * 64;
    int pbase = blockIdx.x * SCAT_PPB;
    int tid = threadIdx.x;
    int td = tid & 15;
    int tc = tid >> 4;
    unsigned long long acc2[4][2];
#pragma unroll
    for (int c = 0; c < 4; c++) { acc2[c][0] = 0ull; acc2[c][1] = 0ull; }
    float cnt[4] = {0.0f, 0.0f, 0.0f, 0.0f};
    for (int s = 0; s < SCAT_PPB; s += SCAT_SUB) {
        // stage 32 pts x 64 dims (512 float4, 2 per thread, coalesced)
#pragma unroll
        for (int u = 0; u < 2; u++) {
            int idx = tid + u * 256;
            int row = idx >> 4;
            int c4 = idx & 15;
            float4 v = *(const float4*)&X[(size_t)(pbase + s + row) * DIM + dbase + c4 * 4];
            *(float4*)&Xs[row][c4 * 4] = v;
        }
        if (tid < SCAT_SUB) lbl[tid] = g_labels[r * NPTS + pbase + s + tid];
        __syncthreads();
#pragma unroll 4
        for (int p = 0; p < SCAT_SUB; p++) {
            int l = lbl[p];                              // uniform -> broadcast
            unsigned dd = (unsigned)(l - tc * 4);
            if (dd < 4u) {
                unsigned long long x01 = *(const unsigned long long*)&Xs[p][td * 4];
                unsigned long long x23 = *(const unsigned long long*)&Xs[p][td * 4 + 2];
#pragma unroll
                for (int c = 0; c < 4; c++) {
                    if (dd == (unsigned)c) {             // predicated adds
                        add2(acc2[c][0], x01);
                        add2(acc2[c][1], x23);
                        cnt[c] += 1.0f;
                    }
                }
            }
        }
        __syncthreads();
    }
    // flush: 16 spread global atomics per thread; counts once (y==0, td==0)
#pragma unroll
    for (int c = 0; c < 4; c++) {
        int cl = tc * 4 + c;
        size_t base = (size_t)(r * NC + cl) * DIM + dbase + td * 4;
        float lo, hi;
        unpack2(acc2[c][0], lo, hi);
        atomicAdd(&g_sums[base + 0], lo);
        atomicAdd(&g_sums[base + 1], hi);
        unpack2(acc2[c][1], lo, hi);
        atomicAdd(&g_sums[base + 2], lo);
        atomicAdd(&g_sums[base + 3], hi);
        if (blockIdx.y == 0 && td == 0)
            atomicAdd(&g_counts[r * NC + cl], cnt[c]);
    }
}

// ---------------- kmeans: centroid update + norms; re-zero accumulators for next iter ----------------
__global__ void update_kernel() {
    int rc = blockIdx.x;
    float cnt = g_counts[rc];
    float v = g_cent[(size_t)rc * DIM + threadIdx.x];
    if (cnt > 0.0f) v = g_sums[(size_t)rc * DIM + threadIdx.x] / fmaxf(cnt, 1.0f);
    g_cent[(size_t)rc * DIM + threadIdx.x] = v;
    g_sums[(size_t)rc * DIM + threadIdx.x] = 0.0f;
    if (threadIdx.x == 0) g_counts[rc] = 0.0f;
    __shared__ float red[256];
    red[threadIdx.x] = v * v;
    __syncthreads();
    for (int s = 128; s > 0; s >>= 1) {
        if (threadIdx.x < s) red[threadIdx.x] += red[threadIdx.x + s];
        __syncthreads();
    }
    if (threadIdx.x == 0) g_cnorm[rc] = red[0];
}

// ---------------- big GEMM: sim = student @ teacher^T (+10 on diag) ----------------
// 128x128 tiles, Bk=8, 256 threads, double-buffered smem + register prefetch.
__global__ void gemm_sim_kernel(const float* __restrict__ A, const float* __restrict__ B) {
    __shared__ float As[2][8][128];
    __shared__ float Bs[2][8][128];
    int bi = blockIdx.y * 128, bj = blockIdx.x * 128;
    int tid = threadIdx.x;
    int tx = tid & 15, ty = tid >> 4;
    unsigned long long acc2[8][4];
#pragma unroll
    for (int i = 0; i < 8; i++)
#pragma unroll
        for (int j = 0; j < 4; j++) acc2[i][j] = 0ull;
    int lr = tid >> 1;
    int kq = (tid & 1) * 4;
    const float* Arow = A + (size_t)(bi + lr) * DIM + kq;
    const float* Brow = B + (size_t)(bj + lr) * DIM + kq;
    {
        float4 a4 = *(const float4*)Arow;
        float4 b4 = *(const float4*)Brow;
        As[0][kq + 0][lr] = a4.x; As[0][kq + 1][lr] = a4.y;
        As[0][kq + 2][lr] = a4.z; As[0][kq + 3][lr] = a4.w;
        Bs[0][kq + 0][lr] = b4.x; Bs[0][kq + 1][lr] = b4.y;
        Bs[0][kq + 2][lr] = b4.z; Bs[0][kq + 3][lr] = b4.w;
    }
    __syncthreads();
    for (int k0 = 0; k0 < DIM; k0 += 8) {
        int buf = (k0 >> 3) & 1;
        bool has_next = (k0 + 8 < DIM);
        float4 a4n, b4n;
        if (has_next) {
            a4n = *(const float4*)(Arow + k0 + 8);
            b4n = *(const float4*)(Brow + k0 + 8);
        }
#pragma unroll
        for (int kk = 0; kk < 8; kk++) {
            unsigned long long a2[8], b2[4];
#pragma unroll
            for (int i = 0; i < 8; i++) a2[i] = dup2(As[buf][kk][ty * 8 + i]);
#pragma unroll
            for (int j = 0; j < 4; j++) {
                float2 b = *(const float2*)&Bs[buf][kk][tx * 8 + j * 2];
                b2[j] = pack2(b.x, b.y);
            }
#pragma unroll
            for (int i = 0; i < 8; i++)
#pragma unroll
                for (int j = 0; j < 4; j++) ffma2(acc2[i][j], a2[i], b2[j]);
        }
        if (has_next) {
            int nb = buf ^ 1;
            As[nb][kq + 0][lr] = a4n.x; As[nb][kq + 1][lr] = a4n.y;
            As[nb][kq + 2][lr] = a4n.z; As[nb][kq + 3][lr] = a4n.w;
            Bs[nb][kq + 0][lr] = b4n.x; Bs[nb][kq + 1][lr] = b4n.y;
            Bs[nb][kq + 2][lr] = b4n.z; Bs[nb][kq + 3][lr] = b4n.w;
            __syncthreads();
        }
    }
#pragma unroll
    for (int i = 0; i < 8; i++) {
        int gi = bi + ty * 8 + i;
#pragma unroll
        for (int j = 0; j < 4; j++) {
            int gj = bj + tx * 8 + j * 2;
            float lo, hi;
            unpack2(acc2[i][j], lo, hi);
            if (gi == gj) lo += 10.0f;
            if (gi == gj + 1) hi += 10.0f;
            float2 vv = make_float2(lo, hi);
            *(float2*)&g_sim[(size_t)gi * NPTS + gj] = vv;
        }
    }
}

// ---------------- top-8 per row ----------------
__global__ void topk_kernel() {
    int row = blockIdx.x;
    const float4* s4 = (const float4*)(g_sim + (size_t)row * NPTS);
    int tid = threadIdx.x;
    float v[TK];
    int id[TK];
#pragma unroll
    for (int t = 0; t < TK; t++) { v[t] = -1e30f; id[t] = 0x7fffffff; }
    for (int q = tid; q < NPTS / 4; q += 256) {
        float4 x4 = s4[q];
        float xs[4] = {x4.x, x4.y, x4.z, x4.w};
#pragma unroll
        for (int e = 0; e < 4; e++) {
            float x = xs[e];
            if (x > v[TK - 1]) {
                int j = q * 4 + e;
                v[TK - 1] = x; id[TK - 1] = j;
#pragma unroll
                for (int t = TK - 1; t > 0; t--) {
                    if (v[t] > v[t - 1]) {
                        float tv = v[t]; v[t] = v[t - 1]; v[t - 1] = tv;
                        int ti = id[t]; id[t] = id[t - 1]; id[t - 1] = ti;
                    }
                }
            }
        }
    }
    __shared__ float sv[256 * TK];
    __shared__ int si[256 * TK];
#pragma unroll
    for (int t = 0; t < TK; t++) { sv[tid * TK + t] = v[t]; si[tid * TK + t] = id[t]; }
    __syncthreads();
    for (int half = 128; half >= 1; half >>= 1) {
        float ov[TK];
        int oi[TK];
        if (tid < half) {
            int ai = 0, bi = 0;
#pragma unroll
            for (int t = 0; t < TK; t++) {
                float av = sv[tid * TK + ai], bv = sv[(tid + half) * TK + bi];
                int aid = si[tid * TK + ai], bid = si[(tid + half) * TK + bi];
                bool takeA = (av > bv) || (av == bv && aid <= bid);
                if (takeA) { ov[t] = av; oi[t] = aid; ai++; }
                else       { ov[t] = bv; oi[t] = bid; bi++; }
            }
#pragma unroll
            for (int t = 0; t < TK; t++) { sv[tid * TK + t] = ov[t]; si[tid * TK + t] = oi[t]; }
        }
        __syncthreads();
    }
    if (tid < TK) {
        g_Dknn[row * TK + tid] = sv[tid];
        g_Iknn[row * TK + tid] = si[tid];
    }
}

// ---------------- finalize: mask + outputs ----------------
__global__ void finalize_kernel(float* __restrict__ out) {
    int t = blockIdx.x * blockDim.x + threadIdx.x;
    if (t >= NPTS * TK) return;
    int i = t >> 3;
    int I = g_Iknn[t];
    unsigned code = (unsigned)i * NPTS + (unsigned)I;
    bool adj = (g_bitmap[code >> 5] >> (code & 31)) & 1u;
    bool close = false;
#pragma unroll
    for (int r = 0; r < KR; r++)
        close = close || (g_labels[r * NPTS + i] == g_labels[r * NPTS + I]);
    out[t] = (float)I;
    out[NPTS * TK + t] = (adj || close) ? 1.0f : 0.0f;
    out[2 * NPTS * TK + t] = g_Dknn[t];
}

// ---------------- launch ----------------
extern "C" void kernel_launch(void* const* d_in, const int* in_sizes, int n_in,
                              void* d_out, int out_size) {
    const float* student = (const float*)d_in[0];
    const float* teacher = (const float*)d_in[1];
    const int* eidx      = (const int*)d_in[2];
    const int* kinit_idx = (const int*)d_in[3];
    float* out = (float*)d_out;
    int E = in_sizes[2] / 2;

    void* bmp_p;
    cudaGetSymbolAddress(&bmp_p, g_bitmap);

    // adjacency bitmap
    cudaMemsetAsync(bmp_p, 0, (size_t)NPTS * NPTS / 8);
    set_edges_kernel<<<(E + 255) / 256, 256>>>(eidx, E);

    // kmeans (KR parallel runs, NITER sequential Lloyd steps)
    kinit_kernel<<<KR * NC, 256>>>(teacher, kinit_idx);
    for (int it = 0; it < NITER; it++) {
        assign_kernel<<<dim3(NPTS / 128, KR), 256>>>(teacher);
        scatter_kernel<<<dim3(SCAT_PC, DIM / 64, KR), 256>>>(teacher);
        update_kernel<<<KR * NC, 256>>>();
    }
    assign_kernel<<<dim3(NPTS / 128, KR), 256>>>(teacher);  // final labels

    // similarity + top-k
    gemm_sim_kernel<<<dim3(NPTS / 128, NPTS / 128), 256>>>(student, teacher);
    topk_kernel<<<NPTS, 256>>>();

    // outputs
    finalize_kernel<<<(NPTS * TK + 255) / 256, 256>>>(out);
}